// round 6
// baseline (speedup 1.0000x reference)
#include <cuda_runtime.h>

#define BB 4
#define NN 128
#define DD 128
#define EPS 1e-6f

// scratch for x = dense2(glu(dense1(rmsnorm(q))))  : (B, N, 3D) floats
__device__ float g_x[BB * NN * 3 * DD];

// ---------------------------------------------------------------------------
// Phase A: per-row RMSNorm -> GEMM1 (D->2D) -> GLU -> GEMM2 (D->3D) -> g_x
// Also initializes out with q / mu (phaseB accumulates into out atomically).
// 4 rows per block, 256 threads, warp-cooperative GEMV (8 lanes per output).
// ---------------------------------------------------------------------------
__global__ __launch_bounds__(256) void phaseA_kernel(
    const float* __restrict__ q,
    const float* __restrict__ mu,
    const float* __restrict__ norm_w,
    const float* __restrict__ W1,
    const float* __restrict__ b1,
    const float* __restrict__ W2,
    const float* __restrict__ b2,
    float* __restrict__ out)
{
    __shared__ float hs[4][DD];      // normed input
    __shared__ float ys[4][2 * DD];  // GEMM1 output
    __shared__ float h2s[4][DD];     // GLU output
    __shared__ float xs[4][3 * DD];  // GEMM2 output staging
    __shared__ float rms[4];

    const int tid = threadIdx.x;
    const int row0 = blockIdx.x * 4;
    const int w = tid >> 5, l = tid & 31;
    const int og = l >> 3, ls = l & 7;

    // init out with q and mu (phaseB adds dq/dmu via atomics)
    {
        const float4* qs = (const float4*)(q) + row0 * (DD / 4);
        float4* oq = (float4*)(out) + row0 * (DD / 4);
        for (int c = tid; c < 4 * (DD / 4); c += 256) oq[c] = qs[c];
        const float4* ms = (const float4*)(mu) + row0 * (3 * DD / 4);
        float4* om = (float4*)(out + BB * NN * DD) + row0 * (3 * DD / 4);
        for (int c = tid; c < 4 * (3 * DD / 4); c += 256) om[c] = ms[c];
    }

    // load q rows into smem
    for (int e = tid; e < 4 * DD; e += 256) {
        int r = e >> 7, c = e & 127;
        hs[r][c] = q[(row0 + r) * DD + c];
    }
    __syncthreads();

    // per-row sum of squares (warp r reduces row r)
    if (w < 4) {
        float s = 0.f;
        #pragma unroll
        for (int c = l; c < DD; c += 32) { float v = hs[w][c]; s += v * v; }
        #pragma unroll
        for (int o = 16; o; o >>= 1) s += __shfl_xor_sync(0xffffffffu, s, o);
        if (l == 0) rms[w] = rsqrtf(s * (1.0f / DD) + EPS);
    }
    __syncthreads();

    for (int e = tid; e < 4 * DD; e += 256) {
        int r = e >> 7, c = e & 127;
        hs[r][c] *= rms[r] * (1.0f + __ldg(norm_w + c));
    }
    __syncthreads();

    // GEMM1: 256 outputs. Warp w covers o in [w*32, w*32+32): 8 passes x 4 outs.
    // Output computed by 8 lanes (ls), each handling 4 float4 of the 32-f4 row.
    #pragma unroll
    for (int p = 0; p < 8; p++) {
        const int o = (w << 5) + (p << 2) + og;
        float a0 = 0.f, a1 = 0.f, a2 = 0.f, a3 = 0.f;
        const float4* wrow = (const float4*)W1 + o * 32;
        #pragma unroll
        for (int it = 0; it < 4; it++) {
            const int d4 = (it << 3) + ls;
            float4 wv = __ldg(wrow + d4);
            float4 v;
            v = ((const float4*)hs[0])[d4]; a0 += wv.x*v.x + wv.y*v.y + wv.z*v.z + wv.w*v.w;
            v = ((const float4*)hs[1])[d4]; a1 += wv.x*v.x + wv.y*v.y + wv.z*v.z + wv.w*v.w;
            v = ((const float4*)hs[2])[d4]; a2 += wv.x*v.x + wv.y*v.y + wv.z*v.z + wv.w*v.w;
            v = ((const float4*)hs[3])[d4]; a3 += wv.x*v.x + wv.y*v.y + wv.z*v.z + wv.w*v.w;
        }
        #pragma unroll
        for (int off = 4; off; off >>= 1) {
            a0 += __shfl_xor_sync(0xffffffffu, a0, off);
            a1 += __shfl_xor_sync(0xffffffffu, a1, off);
            a2 += __shfl_xor_sync(0xffffffffu, a2, off);
            a3 += __shfl_xor_sync(0xffffffffu, a3, off);
        }
        if (ls == 0) {
            const float bb = __ldg(b1 + o);
            ys[0][o] = a0 + bb; ys[1][o] = a1 + bb;
            ys[2][o] = a2 + bb; ys[3][o] = a3 + bb;
        }
    }
    __syncthreads();

    // GLU: h2 = silu(a) * sigmoid(g)
    for (int e = tid; e < 4 * DD; e += 256) {
        int r = e >> 7, c = e & 127;
        float a = ys[r][c];
        float g = ys[r][c + DD];
        float sa = 1.0f / (1.0f + __expf(-a));
        float sg = 1.0f / (1.0f + __expf(-g));
        h2s[r][c] = a * sa * sg;
    }
    __syncthreads();

    // GEMM2: 384 outputs. Warp w covers o in [w*48, w*48+48): 12 passes x 4.
    #pragma unroll
    for (int p = 0; p < 12; p++) {
        const int o = w * 48 + (p << 2) + og;
        float a0 = 0.f, a1 = 0.f, a2 = 0.f, a3 = 0.f;
        const float4* wrow = (const float4*)W2 + o * 32;
        #pragma unroll
        for (int it = 0; it < 4; it++) {
            const int d4 = (it << 3) + ls;
            float4 wv = __ldg(wrow + d4);
            float4 v;
            v = ((const float4*)h2s[0])[d4]; a0 += wv.x*v.x + wv.y*v.y + wv.z*v.z + wv.w*v.w;
            v = ((const float4*)h2s[1])[d4]; a1 += wv.x*v.x + wv.y*v.y + wv.z*v.z + wv.w*v.w;
            v = ((const float4*)h2s[2])[d4]; a2 += wv.x*v.x + wv.y*v.y + wv.z*v.z + wv.w*v.w;
            v = ((const float4*)h2s[3])[d4]; a3 += wv.x*v.x + wv.y*v.y + wv.z*v.z + wv.w*v.w;
        }
        #pragma unroll
        for (int off = 4; off; off >>= 1) {
            a0 += __shfl_xor_sync(0xffffffffu, a0, off);
            a1 += __shfl_xor_sync(0xffffffffu, a1, off);
            a2 += __shfl_xor_sync(0xffffffffu, a2, off);
            a3 += __shfl_xor_sync(0xffffffffu, a3, off);
        }
        if (ls == 0) {
            const float bb = __ldg(b2 + o);
            xs[0][o] = a0 + bb; xs[1][o] = a1 + bb;
            xs[2][o] = a2 + bb; xs[3][o] = a3 + bb;
        }
    }
    __syncthreads();

    // coalesced store of x to g_x
    for (int e = tid; e < 4 * 96; e += 256) {
        int r = e / 96, c = e % 96;
        ((float4*)g_x)[(row0 + r) * 96 + c] = ((const float4*)xs[r])[c];
    }
}

// ---------------------------------------------------------------------------
// Phase B: pairwise accumulation with cp.async double-buffered pipeline.
// Block = (b, 4-i tile, 32-j tile). Grid = 512, 256 threads = 8 warps:
//   warp w: il = w & 3, jh = w >> 2 (which j of the current 2-j stage).
// Stage = 2 j's of {Wij for 4 i's, x, mu} = 1152 float4 = 18432 B. 2 buffers.
// Main loop is pure LDS + FMA; cp.async keeps stages in flight latency-free.
// ---------------------------------------------------------------------------
#define STAGE_F4 1152           // per-stage float4 count
#define STAGE_BYTES (STAGE_F4 * 16)

__device__ __forceinline__ void cp16(unsigned int dst, const void* src) {
    asm volatile("cp.async.cg.shared.global [%0], [%1], 16;" :: "r"(dst), "l"(src));
}

__global__ __launch_bounds__(256, 3) void phaseB_kernel(
    const float* __restrict__ mu,
    const float* __restrict__ Wij,
    const float* __restrict__ dir_ij,
    const float* __restrict__ mask_ij,
    float* __restrict__ out)
{
    __shared__ float4 sStage[2][STAGE_F4];   // 36864 B
    __shared__ float4 psum[4][32][4];        // 8192 B
    __shared__ float smsk[4][32];            // 512 B
    __shared__ float sdir[4][32][3];         // 1536 B

    const int tid = threadIdx.x;
    const int w = tid >> 5, l = tid & 31;
    const int jt = blockIdx.x & 3;
    const int it = (blockIdx.x >> 2) & 31;
    const int b  = blockIdx.x >> 7;
    const int i0 = it * 4;
    const int il = w & 3;
    const int jh = w >> 2;
    const int jb0 = jt * 32;

    // --- stage mask / dir into smem (published by first pipeline sync) ---
    for (int e = tid; e < 128; e += 256) {
        int mil = e >> 5, jl = e & 31;
        smsk[mil][jl] = __ldg(mask_ij + (b * NN + i0 + mil) * NN + jb0 + jl);
    }
    for (int e = tid; e < 384; e += 256) {
        int mil = e / 96, r = e % 96;
        int jl = r / 3, k = r % 3;
        sdir[mil][jl][k] = __ldg(dir_ij + ((b * NN + i0 + mil) * NN + jb0 + jl) * 3 + k);
    }

    // --- precompute per-thread cp.async slot sources/destinations ---
    const float4* Wf4  = (const float4*)Wij;
    const float4* xf4  = (const float4*)g_x;
    const float4* muf4 = (const float4*)mu;
    const float4* slotSrc[5];
    unsigned int slotDst[5];
    unsigned int sbase = (unsigned int)__cvta_generic_to_shared(&sStage[0][0]);
    #pragma unroll
    for (int k = 0; k < 5; k++) {
        int e = tid + k * 256;
        const float4* src = 0;
        if (e < STAGE_F4) {
            int jj = (e >= 576) ? 1 : 0;
            int r = e - jj * 576;
            int j0 = jb0 + jj;
            if (r < 384) {
                int sil = r / 96, c = r % 96;
                src = Wf4 + ((size_t)(b * NN + i0 + sil) * NN + j0) * 96 + c;
            } else if (r < 480) {
                src = xf4 + (size_t)(b * NN + j0) * 96 + (r - 384);
            } else {
                src = muf4 + (size_t)(b * NN + j0) * 96 + (r - 480);
            }
        }
        slotSrc[k] = src;
        slotDst[k] = sbase + (unsigned int)e * 16u;
    }
    const bool slot4 = (tid < 128);  // e = tid + 1024 < 1152

    // --- issue a stage: s in [0,16), buf = s & 1; j pair advances by 192 f4 ---
#define ISSUE_STAGE(s)                                                   \
    {                                                                    \
        const unsigned int bo = ((s) & 1) * (unsigned int)STAGE_BYTES;   \
        const int adv = (s) * 192;                                       \
        cp16(slotDst[0] + bo, slotSrc[0] + adv);                         \
        cp16(slotDst[1] + bo, slotSrc[1] + adv);                         \
        cp16(slotDst[2] + bo, slotSrc[2] + adv);                         \
        cp16(slotDst[3] + bo, slotSrc[3] + adv);                         \
        if (slot4) cp16(slotDst[4] + bo, slotSrc[4] + adv);              \
        asm volatile("cp.async.commit_group;" ::: "memory");             \
    }

    ISSUE_STAGE(0)
    ISSUE_STAGE(1)

    float4 accq = make_float4(0.f, 0.f, 0.f, 0.f);
    float4 am0 = accq, am1 = accq, am2 = accq;

    for (int s = 0; s < 16; s++) {
        if (s == 15) asm volatile("cp.async.wait_group 0;" ::: "memory");
        else         asm volatile("cp.async.wait_group 1;" ::: "memory");
        __syncthreads();

        // consume stage s from buf s&1; warp handles j = jb0 + s*2 + jh, row il
        const float4* stg = &sStage[s & 1][jh * 576];
        const int jl = s * 2 + jh;
        const float m  = smsk[il][jl];
        const float d0 = sdir[il][jl][0];
        const float d1 = sdir[il][jl][1];
        const float d2 = sdir[il][jl][2];

        float4 wq = stg[il * 96 + l];
        float4 wr = stg[il * 96 + 32 + l];
        float4 wm = stg[il * 96 + 64 + l];
        float4 xq = stg[384 + l];
        float4 xr = stg[416 + l];
        float4 xm = stg[448 + l];
        float4 mu0 = stg[480 + l];
        float4 mu1 = stg[512 + l];
        float4 mu2 = stg[544 + l];

#define PAINN_COMP(c)                                                   \
        {                                                               \
            accq.c = fmaf(wq.c * xq.c, m, accq.c);                      \
            float t = wr.c * xr.c * m;                                  \
            am0.c = fmaf(t, d0, am0.c);                                 \
            am1.c = fmaf(t, d1, am1.c);                                 \
            am2.c = fmaf(t, d2, am2.c);                                 \
            t = wm.c * xm.c * m;                                        \
            am0.c = fmaf(t, mu0.c, am0.c);                              \
            am1.c = fmaf(t, mu1.c, am1.c);                              \
            am2.c = fmaf(t, mu2.c, am2.c);                              \
        }
        PAINN_COMP(x)
        PAINN_COMP(y)
        PAINN_COMP(z)
        PAINN_COMP(w)
#undef PAINN_COMP

        __syncthreads();   // all warps done with buf s&1 before refill
        if (s + 2 < 16) ISSUE_STAGE(s + 2)
    }

    // --- reduce the two j-halves, then atomicAdd into out ---
    if (jh == 1) {
        psum[il][l][0] = accq;
        psum[il][l][1] = am0;
        psum[il][l][2] = am1;
        psum[il][l][3] = am2;
    }
    __syncthreads();
    if (jh == 0) {
        float4 r[4];
        float4 o0 = psum[il][l][0], o1 = psum[il][l][1];
        float4 o2 = psum[il][l][2], o3 = psum[il][l][3];
        r[0].x = accq.x + o0.x; r[0].y = accq.y + o0.y; r[0].z = accq.z + o0.z; r[0].w = accq.w + o0.w;
        r[1].x = am0.x + o1.x;  r[1].y = am0.y + o1.y;  r[1].z = am0.z + o1.z;  r[1].w = am0.w + o1.w;
        r[2].x = am1.x + o2.x;  r[2].y = am1.y + o2.y;  r[2].z = am1.z + o2.z;  r[2].w = am1.w + o2.w;
        r[3].x = am2.x + o3.x;  r[3].y = am2.y + o3.y;  r[3].z = am2.z + o3.z;  r[3].w = am2.w + o3.w;

        const int bio = b * NN + i0 + il;
        float* oq = out + bio * DD + 4 * l;
        atomicAdd(oq + 0, r[0].x);
        atomicAdd(oq + 1, r[0].y);
        atomicAdd(oq + 2, r[0].z);
        atomicAdd(oq + 3, r[0].w);
        float* om = out + BB * NN * DD + bio * 3 * DD + 4 * l;
        #pragma unroll
        for (int k = 0; k < 3; k++) {
            atomicAdd(om + k * DD + 0, r[k + 1].x);
            atomicAdd(om + k * DD + 1, r[k + 1].y);
            atomicAdd(om + k * DD + 2, r[k + 1].z);
            atomicAdd(om + k * DD + 3, r[k + 1].w);
        }
    }
#undef ISSUE_STAGE
}

// ---------------------------------------------------------------------------
extern "C" void kernel_launch(void* const* d_in, const int* in_sizes, int n_in,
                              void* d_out, int out_size)
{
    const float* q       = (const float*)d_in[0];
    const float* mu      = (const float*)d_in[1];
    const float* Wij     = (const float*)d_in[2];
    const float* dir_ij  = (const float*)d_in[3];
    const float* mask_ij = (const float*)d_in[4];
    const float* norm_w  = (const float*)d_in[5];
    const float* W1      = (const float*)d_in[6];
    const float* b1      = (const float*)d_in[7];
    const float* W2      = (const float*)d_in[8];
    const float* b2      = (const float*)d_in[9];
    float* out = (float*)d_out;

    phaseA_kernel<<<(BB * NN) / 4, 256>>>(q, mu, norm_w, W1, b1, W2, b2, out);
    phaseB_kernel<<<BB * NN, 256>>>(mu, Wij, dir_ij, mask_ij, out);
}

// round 10
// speedup vs baseline: 1.1067x; 1.1067x over previous
#include <cuda_runtime.h>

#define BB 4
#define NN 128
#define DD 128
#define EPS 1e-6f

// scratch for x = dense2(glu(dense1(rmsnorm(q))))  : (B, N, 3D) floats
__device__ float g_x[BB * NN * 3 * DD];

// ---------------------------------------------------------------------------
// Phase A: per-row RMSNorm -> GEMM1 (D->2D) -> GLU -> GEMM2 (D->3D) -> g_x
// Also initializes out with q / mu (phaseB accumulates into out atomically).
// 4 rows per block, 512 threads. Grid = 128 blocks.
// GEMV pair-split: 2 threads per output (each 16 float4 of K), shfl combine.
// ---------------------------------------------------------------------------
__global__ __launch_bounds__(512) void phaseA_kernel(
    const float* __restrict__ q,
    const float* __restrict__ mu,
    const float* __restrict__ norm_w,
    const float* __restrict__ W1,
    const float* __restrict__ b1,
    const float* __restrict__ W2,
    const float* __restrict__ b2,
    float* __restrict__ out)
{
    __shared__ float hs[4][DD];      // normed input
    __shared__ float ys[4][2 * DD];  // GEMM1 output
    __shared__ float h2s[4][DD];     // GLU output
    __shared__ float xs[4][3 * DD];  // GEMM2 output staging
    __shared__ float rms[4];

    const int tid = threadIdx.x;
    const int row0 = blockIdx.x * 4;
    const int w = tid >> 5, l = tid & 31;

    // init out with q and mu (phaseB adds dq/dmu via atomics)
    if (tid < 128) {
        ((float4*)out)[row0 * 32 + tid] = ((const float4*)q)[row0 * 32 + tid];
    }
    if (tid < 384) {
        ((float4*)(out + BB * NN * DD))[row0 * 96 + tid] =
            ((const float4*)mu)[row0 * 96 + tid];
    }

    // load q rows into smem (one element per thread)
    {
        int r = tid >> 7, c = tid & 127;
        hs[r][c] = q[(row0 + r) * DD + c];
    }
    __syncthreads();

    // per-row sum of squares (warps 0..3)
    if (w < 4) {
        float s = 0.f;
        #pragma unroll
        for (int c = l; c < DD; c += 32) { float v = hs[w][c]; s += v * v; }
        #pragma unroll
        for (int o = 16; o; o >>= 1) s += __shfl_xor_sync(0xffffffffu, s, o);
        if (l == 0) rms[w] = rsqrtf(s * (1.0f / DD) + EPS);
    }
    __syncthreads();

    {
        int r = tid >> 7, c = tid & 127;
        hs[r][c] *= rms[r] * (1.0f + __ldg(norm_w + c));
    }
    __syncthreads();

    // GEMM1: 256 outputs, pair-split: o = tid>>1, kh = tid&1 (16 f4 each)
    {
        const int o = tid >> 1, kh = tid & 1;
        float a0 = 0.f, a1 = 0.f, a2 = 0.f, a3 = 0.f;
        const float4* wrow = (const float4*)W1 + o * 32 + kh * 16;
        const float4* h0 = (const float4*)hs[0] + kh * 16;
        const float4* h1 = (const float4*)hs[1] + kh * 16;
        const float4* h2 = (const float4*)hs[2] + kh * 16;
        const float4* h3 = (const float4*)hs[3] + kh * 16;
        #pragma unroll
        for (int d4 = 0; d4 < 16; d4++) {
            float4 wv = __ldg(wrow + d4);
            float4 v;
            v = h0[d4]; a0 += wv.x*v.x + wv.y*v.y + wv.z*v.z + wv.w*v.w;
            v = h1[d4]; a1 += wv.x*v.x + wv.y*v.y + wv.z*v.z + wv.w*v.w;
            v = h2[d4]; a2 += wv.x*v.x + wv.y*v.y + wv.z*v.z + wv.w*v.w;
            v = h3[d4]; a3 += wv.x*v.x + wv.y*v.y + wv.z*v.z + wv.w*v.w;
        }
        a0 += __shfl_xor_sync(0xffffffffu, a0, 1);
        a1 += __shfl_xor_sync(0xffffffffu, a1, 1);
        a2 += __shfl_xor_sync(0xffffffffu, a2, 1);
        a3 += __shfl_xor_sync(0xffffffffu, a3, 1);
        if (kh == 0) {
            const float bb = __ldg(b1 + o);
            ys[0][o] = a0 + bb; ys[1][o] = a1 + bb;
            ys[2][o] = a2 + bb; ys[3][o] = a3 + bb;
        }
    }
    __syncthreads();

    // GLU: h2 = silu(a) * sigmoid(g)   (512 elems = 1/thread)
    {
        int r = tid >> 7, c = tid & 127;
        float a = ys[r][c];
        float g = ys[r][c + DD];
        float sa = 1.0f / (1.0f + __expf(-a));
        float sg = 1.0f / (1.0f + __expf(-g));
        h2s[r][c] = a * sa * sg;
    }
    __syncthreads();

    // GEMM2: 384 outputs, pair-split -> 768 tasks over 2 passes
    #pragma unroll
    for (int p = 0; p < 2; p++) {
        const int tt = tid + p * 512;
        if (tt < 768) {
            const int o = tt >> 1, kh = tt & 1;
            float a0 = 0.f, a1 = 0.f, a2 = 0.f, a3 = 0.f;
            const float4* wrow = (const float4*)W2 + o * 32 + kh * 16;
            const float4* h0 = (const float4*)h2s[0] + kh * 16;
            const float4* h1 = (const float4*)h2s[1] + kh * 16;
            const float4* h2 = (const float4*)h2s[2] + kh * 16;
            const float4* h3 = (const float4*)h2s[3] + kh * 16;
            #pragma unroll
            for (int d4 = 0; d4 < 16; d4++) {
                float4 wv = __ldg(wrow + d4);
                float4 v;
                v = h0[d4]; a0 += wv.x*v.x + wv.y*v.y + wv.z*v.z + wv.w*v.w;
                v = h1[d4]; a1 += wv.x*v.x + wv.y*v.y + wv.z*v.z + wv.w*v.w;
                v = h2[d4]; a2 += wv.x*v.x + wv.y*v.y + wv.z*v.z + wv.w*v.w;
                v = h3[d4]; a3 += wv.x*v.x + wv.y*v.y + wv.z*v.z + wv.w*v.w;
            }
            a0 += __shfl_xor_sync(0xffffffffu, a0, 1);
            a1 += __shfl_xor_sync(0xffffffffu, a1, 1);
            a2 += __shfl_xor_sync(0xffffffffu, a2, 1);
            a3 += __shfl_xor_sync(0xffffffffu, a3, 1);
            if (kh == 0) {
                const float bb = __ldg(b2 + o);
                xs[0][o] = a0 + bb; xs[1][o] = a1 + bb;
                xs[2][o] = a2 + bb; xs[3][o] = a3 + bb;
            }
        }
    }
    __syncthreads();

    // coalesced store of x to g_x (384 f4)
    if (tid < 384) {
        int r = tid / 96, c = tid % 96;
        ((float4*)g_x)[(row0 + r) * 96 + c] = ((const float4*)xs[r])[c];
    }
}

// ---------------------------------------------------------------------------
// Phase B: pairwise accumulation, 4-stage cp.async ring, 1 j per stage.
// Block = (b, 4-i tile, 32-j tile). Grid = 512, 256 threads = 8 warps:
//   warp w: il = w & 3 (row), h = w >> 2 (channel half: 64 channels).
//   lane l owns channels [h*64 + 2l, h*64 + 2l + 1] (float2 granularity).
// Each warp owns disjoint (i, channel) -> no cross-warp reduction needed.
// One __syncthreads per stage (issue(s+3) overwrites slot consumed at s-1,
// which every warp finished before the barrier of iteration s).
// ---------------------------------------------------------------------------
#define SJ_F4 576
#define SJ_BYTES 9216

__device__ __forceinline__ void cp16(unsigned int dst, const void* src) {
    asm volatile("cp.async.cg.shared.global [%0], [%1], 16;" :: "r"(dst), "l"(src));
}

__global__ __launch_bounds__(256, 4) void phaseB_kernel(
    const float* __restrict__ mu,
    const float* __restrict__ Wij,
    const float* __restrict__ dir_ij,
    const float* __restrict__ mask_ij,
    float* __restrict__ out)
{
    __shared__ float4 sStage[4][SJ_F4];   // 36864 B
    __shared__ float smsk[4][32];         // 512 B
    __shared__ float sdir[4][32][3];      // 1536 B

    const int tid = threadIdx.x;
    const int w = tid >> 5, l = tid & 31;
    const int jt = blockIdx.x & 3;
    const int it = (blockIdx.x >> 2) & 31;
    const int b  = blockIdx.x >> 7;
    const int i0 = it * 4;
    const int il = w & 3;
    const int h  = w >> 2;
    const int jb0 = jt * 32;

    // --- stage mask / dir into smem (visible after first barrier) ---
    if (tid < 128) {
        int mil = tid >> 5, jl = tid & 31;
        smsk[mil][jl] = __ldg(mask_ij + (b * NN + i0 + mil) * NN + jb0 + jl);
    }
    for (int e = tid; e < 384; e += 256) {
        int mil = e / 96, r = e % 96;
        int jl = r / 3, k = r % 3;
        sdir[mil][jl][k] = __ldg(dir_ij + ((b * NN + i0 + mil) * NN + jb0 + jl) * 3 + k);
    }

    // --- per-thread cp.async slots (all sources advance by 96 f4 per j) ---
    const float4* Wf4  = (const float4*)Wij;
    const float4* xf4  = (const float4*)g_x;
    const float4* muf4 = (const float4*)mu;
    const float4* slotSrc[3];
    unsigned int slotDst[3];
    unsigned int sbase = (unsigned int)__cvta_generic_to_shared(&sStage[0][0]);
    #pragma unroll
    for (int k = 0; k < 3; k++) {
        int e = tid + k * 256;
        const float4* src = 0;
        if (e < SJ_F4) {
            if (e < 384) {
                src = Wf4 + ((size_t)(b * NN + i0 + e / 96) * NN + jb0) * 96 + (e % 96);
            } else if (e < 480) {
                src = xf4 + (size_t)(b * NN + jb0) * 96 + (e - 384);
            } else {
                src = muf4 + (size_t)(b * NN + jb0) * 96 + (e - 480);
            }
        }
        slotSrc[k] = src;
        slotDst[k] = sbase + (unsigned int)e * 16u;
    }
    const bool slot2 = (tid < 64);

#define ISSUE_STAGE(s)                                                   \
    {                                                                    \
        const unsigned int bo = ((s) & 3) * (unsigned int)SJ_BYTES;      \
        const int adv = (s) * 96;                                        \
        cp16(slotDst[0] + bo, slotSrc[0] + adv);                         \
        cp16(slotDst[1] + bo, slotSrc[1] + adv);                         \
        if (slot2) cp16(slotDst[2] + bo, slotSrc[2] + adv);              \
        asm volatile("cp.async.commit_group;" ::: "memory");             \
    }

    ISSUE_STAGE(0)
    ISSUE_STAGE(1)
    ISSUE_STAGE(2)

    float2 accq = make_float2(0.f, 0.f);
    float2 am0 = accq, am1 = accq, am2 = accq;

    const int co = h * 32 + l;   // float2 index within a 64-f2 segment

    for (int s = 0; s < 32; s++) {
        if (s < 30)      asm volatile("cp.async.wait_group 2;" ::: "memory");
        else if (s == 30) asm volatile("cp.async.wait_group 1;" ::: "memory");
        else              asm volatile("cp.async.wait_group 0;" ::: "memory");
        __syncthreads();

        const float2* stg2 = (const float2*)&sStage[s & 3][0];
        const float m  = smsk[il][s];
        const float d0 = sdir[il][s][0];
        const float d1 = sdir[il][s][1];
        const float d2 = sdir[il][s][2];

        float2 wq = stg2[il * 192 + co];
        float2 wr = stg2[il * 192 + 64 + co];
        float2 wm = stg2[il * 192 + 128 + co];
        float2 xq = stg2[768 + co];
        float2 xr = stg2[832 + co];
        float2 xm = stg2[896 + co];
        float2 m0 = stg2[960 + co];
        float2 m1 = stg2[1024 + co];
        float2 m2 = stg2[1088 + co];

#define PAINN_COMP(c)                                                   \
        {                                                               \
            accq.c = fmaf(wq.c * xq.c, m, accq.c);                      \
            float t = wr.c * xr.c * m;                                  \
            am0.c = fmaf(t, d0, am0.c);                                 \
            am1.c = fmaf(t, d1, am1.c);                                 \
            am2.c = fmaf(t, d2, am2.c);                                 \
            t = wm.c * xm.c * m;                                        \
            am0.c = fmaf(t, m0.c, am0.c);                               \
            am1.c = fmaf(t, m1.c, am1.c);                               \
            am2.c = fmaf(t, m2.c, am2.c);                               \
        }
        PAINN_COMP(x)
        PAINN_COMP(y)
#undef PAINN_COMP

        if (s < 29) ISSUE_STAGE(s + 3)
    }
#undef ISSUE_STAGE

    // --- direct atomic epilogue: warp owns disjoint (i, channel pair) ---
    const int bio = b * NN + i0 + il;
    const int c0 = 2 * co;                 // first of 2 channels
    float* oq = out + bio * DD + c0;
    atomicAdd(oq + 0, accq.x);
    atomicAdd(oq + 1, accq.y);
    float* om = out + BB * NN * DD + bio * 3 * DD + c0;
    atomicAdd(om + 0,          am0.x);
    atomicAdd(om + 1,          am0.y);
    atomicAdd(om + DD + 0,     am1.x);
    atomicAdd(om + DD + 1,     am1.y);
    atomicAdd(om + 2 * DD + 0, am2.x);
    atomicAdd(om + 2 * DD + 1, am2.y);
}

// ---------------------------------------------------------------------------
extern "C" void kernel_launch(void* const* d_in, const int* in_sizes, int n_in,
                              void* d_out, int out_size)
{
    const float* q       = (const float*)d_in[0];
    const float* mu      = (const float*)d_in[1];
    const float* Wij     = (const float*)d_in[2];
    const float* dir_ij  = (const float*)d_in[3];
    const float* mask_ij = (const float*)d_in[4];
    const float* norm_w  = (const float*)d_in[5];
    const float* W1      = (const float*)d_in[6];
    const float* b1      = (const float*)d_in[7];
    const float* W2      = (const float*)d_in[8];
    const float* b2      = (const float*)d_in[9];
    float* out = (float*)d_out;

    phaseA_kernel<<<(BB * NN) / 4, 512>>>(q, mu, norm_w, W1, b1, W2, b2, out);
    phaseB_kernel<<<BB * NN, 256>>>(mu, Wij, dir_ij, mask_ij, out);
}